// round 4
// baseline (speedup 1.0000x reference)
#include <cuda_runtime.h>
#include <cfloat>
#include <cstddef>

#define NPTS 2048
#define BATCH 4
#define KNN 20

// ---------------- scratch (device globals; no allocation allowed) ----------
__device__ float g_x0[BATCH * 3 * NPTS];
// concat feature buffer: (B, 512, N). x1 @ ch 0, x2 @ 64, x3 @ 128, x4 @ 256
__device__ float g_xcat[(size_t)BATCH * 512 * NPTS];
__device__ float g_xx[BATCH * NPTS];
__device__ int   g_knn[BATCH * NPTS * KNN];
__device__ float g_Y[BATCH * NPTS * 256];                // n-major, stride 256
__device__ float g_Z[BATCH * NPTS * 256];
__device__ float g_h5[(size_t)BATCH * NPTS * 1024];      // 32 MB
__device__ float g_f[BATCH * 2048];
__device__ float g_fc1[BATCH * 512];

__device__ __forceinline__ float lrelu(float v) { return v > 0.f ? v : 0.2f * v; }
#define BN_RSQ 0.99999500003749968750f  /* rsqrt(1+1e-5) */
#define CAT_BSTR (512 * NPTS)

// ---------------- transpose points (B,N,3) -> (B,3,N) ----------------------
__global__ void k_transpose(const float* __restrict__ pts) {
    int i = blockIdx.x * blockDim.x + threadIdx.x;
    if (i < BATCH * NPTS) {
        int b = i / NPTS, n = i % NPTS;
        #pragma unroll
        for (int c = 0; c < 3; c++)
            g_x0[(b * 3 + c) * NPTS + n] = pts[(b * NPTS + n) * 3 + c];
    }
}

// ---------------- row norms ------------------------------------------------
__global__ void k_xx(const float* __restrict__ feat, int C, int bstr) {
    int i = blockIdx.x * blockDim.x + threadIdx.x;
    if (i < BATCH * NPTS) {
        int b = i / NPTS, n = i % NPTS;
        const float* f = feat + (size_t)b * bstr + n;
        float s = 0.f;
        for (int c = 0; c < C; c++) { float v = f[(size_t)c * NPTS]; s = fmaf(v, v, s); }
        g_xx[i] = s;
    }
}

// ---------------- FUSED distance GEMM + top-K ------------------------------
// grid (N/64, B), 256 threads, dynamic smem.
// Per block: 64 rows. Loop over 8 j-tiles of 256:
//   GEMM 64x256 (8x8/thread, K-chunk 8) -> S = 2 X^T X - xx_i - xx_j in smem
//   per-warp incremental top-20 for 8 rows (warp-parallel insert).
// Candidate order is ascending j; strict > vs kth; position counts >= so
// equal values keep the earlier index -> exact jax.lax.top_k semantics.
__global__ void k_dist_topk(const float* __restrict__ feat, int C, int bstr) {
    extern __shared__ float sm[];
    float* As = sm;                   // 8*64
    float* Bs = As + 8 * 64;          // 8*256
    float* Ss = Bs + 8 * 256;         // 64*256
    float* Lv = Ss + 64 * 256;        // 64*KNN
    int*   Li = (int*)(Lv + 64 * KNN);// 64*KNN

    int b = blockIdx.y;
    int i0 = blockIdx.x * 64;
    const float* fb = feat + (size_t)b * bstr;
    int tid = threadIdx.x;
    int lane = tid & 31, warp = tid >> 5;     // warp: 0..7
    const unsigned FULL = 0xffffffffu;

    for (int e = tid; e < 64 * KNN; e += 256) {
        Lv[e] = -FLT_MAX;
        Li[e] = 0x7FFFFFFF;
    }
    __syncthreads();

    for (int j0 = 0; j0 < NPTS; j0 += 256) {
        // ---- GEMM 64x256 ----
        float acc[8][8] = {};
        for (int c0 = 0; c0 < C; c0 += 8) {
            if (tid < 128) {                       // As: 8x64 floats
                int kk = tid >> 4, ii = (tid & 15) * 4;
                int c = c0 + kk;
                float4 v = {0.f, 0.f, 0.f, 0.f};
                if (c < C) v = *(const float4*)&fb[(size_t)c * NPTS + i0 + ii];
                *(float4*)&As[kk * 64 + ii] = v;
            }
            {                                       // Bs: 8x256 floats
                int kk = warp;
                int c = c0 + kk;
                float4 v0 = {0.f, 0.f, 0.f, 0.f}, v1 = v0;
                if (c < C) {
                    v0 = *(const float4*)&fb[(size_t)c * NPTS + j0 + lane * 4];
                    v1 = *(const float4*)&fb[(size_t)c * NPTS + j0 + 128 + lane * 4];
                }
                *(float4*)&Bs[kk * 256 + lane * 4] = v0;
                *(float4*)&Bs[kk * 256 + 128 + lane * 4] = v1;
            }
            __syncthreads();
            #pragma unroll
            for (int kk = 0; kk < 8; kk++) {
                float a[8], bb[8];
                *(float4*)&a[0] = *(const float4*)&As[kk * 64 + warp * 8];
                *(float4*)&a[4] = *(const float4*)&As[kk * 64 + warp * 8 + 4];
                *(float4*)&bb[0] = *(const float4*)&Bs[kk * 256 + lane * 8];
                *(float4*)&bb[4] = *(const float4*)&Bs[kk * 256 + lane * 8 + 4];
                #pragma unroll
                for (int r = 0; r < 8; r++)
                    #pragma unroll
                    for (int s = 0; s < 8; s++)
                        acc[r][s] = fmaf(a[r], bb[s], acc[r][s]);
            }
            __syncthreads();
        }
        // ---- epilogue: S = 2*acc - xi - xj -> smem ----
        float xj[8];
        #pragma unroll
        for (int s = 0; s < 8; s++) xj[s] = g_xx[b * NPTS + j0 + lane * 8 + s];
        #pragma unroll
        for (int r = 0; r < 8; r++) {
            int i = i0 + warp * 8 + r;
            float xi = g_xx[b * NPTS + i];
            float o[8];
            #pragma unroll
            for (int s = 0; s < 8; s++) o[s] = 2.f * acc[r][s] - xi - xj[s];
            *(float4*)&Ss[(warp * 8 + r) * 256 + lane * 8] = *(float4*)&o[0];
            *(float4*)&Ss[(warp * 8 + r) * 256 + lane * 8 + 4] = *(float4*)&o[4];
        }
        __syncthreads();
        // ---- top-k update: warp owns rows warp*8 .. warp*8+7 ----
        #pragma unroll 1
        for (int rr = 0; rr < 8; rr++) {
            int r = warp * 8 + rr;
            float kth = Lv[r * KNN + KNN - 1];
            #pragma unroll 1
            for (int m = 0; m < 8; m++) {
                float v = Ss[r * 256 + lane + 32 * m];
                unsigned mask = __ballot_sync(FULL, v > kth);
                while (mask) {
                    int src = __ffs(mask) - 1;
                    mask &= mask - 1;
                    float vs = __shfl_sync(FULL, v, src);
                    if (vs > kth) {                 // recheck vs updated kth
                        int js = j0 + src + 32 * m;
                        float Lq = (lane < KNN) ? Lv[r * KNN + lane] : -FLT_MAX;
                        int   Iq = (lane < KNN) ? Li[r * KNN + lane] : 0x7FFFFFFF;
                        unsigned bef = __ballot_sync(FULL, (lane < KNN) && (Lq >= vs));
                        int p = __popc(bef);
                        float sv = __shfl_up_sync(FULL, Lq, 1);
                        int   si = __shfl_up_sync(FULL, Iq, 1);
                        float nLq = (lane < p) ? Lq : (lane == p ? vs : sv);
                        int   nIq = (lane < p) ? Iq : (lane == p ? js : si);
                        if (lane < KNN) {
                            Lv[r * KNN + lane] = nLq;
                            Li[r * KNN + lane] = nIq;
                        }
                        kth = __shfl_sync(FULL, nLq, KNN - 1);
                    }
                }
            }
        }
        __syncthreads();
    }
    // ---- write results (lists already sorted desc, ties index-asc) ----
    #pragma unroll 1
    for (int rr = 0; rr < 8; rr++) {
        int r = warp * 8 + rr;
        if (lane < KNN)
            g_knn[((size_t)b * NPTS + i0 + r) * KNN + lane] = Li[r * KNN + lane];
    }
}

// ---------------- Y = W2 X, Z = (W1-W2) X ; stored n-major stride 256 ------
// grid (N/64, Cout/64, B), 256 threads
__global__ void k_yz(const float* __restrict__ feat, const float* __restrict__ W,
                     int C, int Cout, int bstr) {
    __shared__ float As[16][64];
    __shared__ float B1[16][64];
    __shared__ float B2[16][64];
    int b = blockIdx.z;
    int n0 = blockIdx.x * 64, o0 = blockIdx.y * 64;
    const float* fb = feat + (size_t)b * bstr;
    int tx = threadIdx.x & 15, ty = threadIdx.x >> 4;
    float aU[4][4] = {}, aY[4][4] = {};
    for (int c0 = 0; c0 < C; c0 += 16) {
        for (int e = threadIdx.x; e < 1024; e += 256) {
            int kk = e >> 6, nn = e & 63;
            int c = c0 + kk;
            As[kk][nn] = (c < C) ? fb[(size_t)c * NPTS + n0 + nn] : 0.f;
        }
        for (int e = threadIdx.x; e < 1024; e += 256) {
            int kk = e & 15, oo = e >> 4;
            int c = c0 + kk;
            float w1 = 0.f, w2 = 0.f;
            if (c < C) {
                const float* wr = W + (size_t)(o0 + oo) * (2 * C);
                w1 = wr[c]; w2 = wr[C + c];
            }
            B1[kk][oo] = w1; B2[kk][oo] = w2;
        }
        __syncthreads();
        #pragma unroll
        for (int kk = 0; kk < 16; kk++) {
            float4 a4 = *(const float4*)&As[kk][ty * 4];
            float4 b14 = *(const float4*)&B1[kk][tx * 4];
            float4 b24 = *(const float4*)&B2[kk][tx * 4];
            float av[4] = {a4.x, a4.y, a4.z, a4.w};
            float b1v[4] = {b14.x, b14.y, b14.z, b14.w};
            float b2v[4] = {b24.x, b24.y, b24.z, b24.w};
            #pragma unroll
            for (int r = 0; r < 4; r++)
                #pragma unroll
                for (int s = 0; s < 4; s++) {
                    aU[r][s] = fmaf(av[r], b1v[s], aU[r][s]);
                    aY[r][s] = fmaf(av[r], b2v[s], aY[r][s]);
                }
        }
        __syncthreads();
    }
    #pragma unroll
    for (int r = 0; r < 4; r++) {
        int n = n0 + ty * 4 + r;
        size_t base = ((size_t)b * NPTS + n) * 256 + o0 + tx * 4;
        float4 y, z;
        y.x = aY[r][0]; y.y = aY[r][1]; y.z = aY[r][2]; y.w = aY[r][3];
        z.x = aU[r][0] - y.x; z.y = aU[r][1] - y.y;
        z.z = aU[r][2] - y.z; z.w = aU[r][3] - y.w;
        *(float4*)&g_Y[base] = y;
        *(float4*)&g_Z[base] = z;
    }
}

// ---------------- gather-max + BN + lrelu -> out slice of g_xcat -----------
// grid (N/32, B), blockDim = Cout
__global__ void k_gather(float* __restrict__ out, const float* __restrict__ gam,
                         const float* __restrict__ bet, int Cout, int bstr) {
    __shared__ int   sidx[32 * KNN];
    __shared__ float sout[256 * 33];
    int b = blockIdx.y, n0 = blockIdx.x * 32;
    for (int e = threadIdx.x; e < 32 * KNN; e += blockDim.x)
        sidx[e] = g_knn[((size_t)b * NPTS + n0) * KNN + e];
    __syncthreads();
    int o = threadIdx.x;
    float sc = gam[o] * BN_RSQ, bi = bet[o];
    const float* Yb = g_Y + (size_t)b * NPTS * 256;
    const float* Zb = g_Z + (size_t)b * NPTS * 256;
    for (int nn = 0; nn < 32; nn++) {
        float m = -FLT_MAX;
        #pragma unroll
        for (int k = 0; k < KNN; k++) {
            int j = sidx[nn * KNN + k];
            m = fmaxf(m, Yb[(size_t)j * 256 + o]);
        }
        float v = Zb[(size_t)(n0 + nn) * 256 + o] + m;
        v = lrelu(fmaf(v, sc, bi));
        sout[o * 33 + nn] = v;
    }
    __syncthreads();
    float* ob = out + (size_t)b * bstr;
    for (int e = threadIdx.x; e < Cout * 32; e += blockDim.x) {
        int oo = e >> 5, nn = e & 31;
        ob[(size_t)oo * NPTS + n0 + nn] = sout[oo * 33 + nn];
    }
}

// ---------------- conv5 (512->1024) + BN + lrelu -> g_h5 (n-major) ---------
// 128x128 tile, 8x8/thread. grid (N/128, 1024/128, B), 256 threads
__global__ void k_conv5(const float* __restrict__ W5, const float* __restrict__ gam,
                        const float* __restrict__ bet) {
    __shared__ float As[8][128];
    __shared__ float Bs[8][128];
    int b = blockIdx.z;
    int n0 = blockIdx.x * 128, o0 = blockIdx.y * 128;
    int tx = threadIdx.x & 15, ty = threadIdx.x >> 4;
    int lr = threadIdx.x & 31, lc = threadIdx.x >> 5;
    int wo = threadIdx.x >> 1, wk = (threadIdx.x & 1) * 4;   // weight-load mapping
    const float* xb = g_xcat + (size_t)b * CAT_BSTR;
    float acc[8][8] = {};
    for (int c0 = 0; c0 < 512; c0 += 8) {
        float4 av = *(const float4*)&xb[(size_t)(c0 + lc) * NPTS + n0 + lr * 4];
        float4 wv = *(const float4*)&W5[(size_t)(o0 + wo) * 512 + c0 + wk];
        *(float4*)&As[lc][lr * 4] = av;
        Bs[wk + 0][wo] = wv.x;
        Bs[wk + 1][wo] = wv.y;
        Bs[wk + 2][wo] = wv.z;
        Bs[wk + 3][wo] = wv.w;
        __syncthreads();
        #pragma unroll
        for (int kk = 0; kk < 8; kk++) {
            float a[8], bb[8];
            *(float4*)&a[0] = *(const float4*)&As[kk][ty * 8];
            *(float4*)&a[4] = *(const float4*)&As[kk][ty * 8 + 4];
            *(float4*)&bb[0] = *(const float4*)&Bs[kk][tx * 8];
            *(float4*)&bb[4] = *(const float4*)&Bs[kk][tx * 8 + 4];
            #pragma unroll
            for (int r = 0; r < 8; r++)
                #pragma unroll
                for (int s = 0; s < 8; s++)
                    acc[r][s] = fmaf(a[r], bb[s], acc[r][s]);
        }
        __syncthreads();
    }
    float sc[8], bi[8];
    #pragma unroll
    for (int s = 0; s < 8; s++) {
        int o = o0 + tx * 8 + s;
        sc[s] = gam[o] * BN_RSQ; bi[s] = bet[o];
    }
    #pragma unroll
    for (int r = 0; r < 8; r++) {
        int n = n0 + ty * 8 + r;
        float o[8];
        #pragma unroll
        for (int s = 0; s < 8; s++) o[s] = lrelu(fmaf(acc[r][s], sc[s], bi[s]));
        float* dst = &g_h5[((size_t)b * NPTS + n) * 1024 + o0 + tx * 8];
        *(float4*)&dst[0] = *(float4*)&o[0];
        *(float4*)&dst[4] = *(float4*)&o[4];
    }
}

// ---------------- global max + mean pool -> g_f (B, 2048) ------------------
__global__ void k_pool() {
    int b = blockIdx.y;
    int o = blockIdx.x * 256 + threadIdx.x;
    const float* h = g_h5 + (size_t)b * NPTS * 1024;
    float mx = -FLT_MAX, sm = 0.f;
    #pragma unroll 8
    for (int n = 0; n < NPTS; n++) {
        float v = h[(size_t)n * 1024 + o];
        mx = fmaxf(mx, v);
        sm += v;
    }
    g_f[b * 2048 + o] = mx;
    g_f[b * 2048 + 1024 + o] = sm * (1.0f / NPTS);
}

// ---------------- fc1: 2048->512, BN + lrelu -------------------------------
__global__ void k_fc1(const float* __restrict__ fw, const float* __restrict__ fb,
                      const float* __restrict__ gam, const float* __restrict__ bet) {
    int b = blockIdx.y;
    int w = threadIdx.x >> 5, lane = threadIdx.x & 31;
    int o = blockIdx.x * 8 + w;
    const float* f = g_f + b * 2048;
    const float* wr = fw + (size_t)o * 2048;
    float acc = 0.f;
    for (int c = lane; c < 2048; c += 32) acc = fmaf(f[c], wr[c], acc);
    #pragma unroll
    for (int s = 16; s > 0; s >>= 1) acc += __shfl_xor_sync(0xffffffffu, acc, s);
    if (lane == 0) {
        float v = acc + fb[o];
        v = lrelu(fmaf(v, gam[o] * BN_RSQ, bet[o]));
        g_fc1[b * 512 + o] = v;
    }
}

// ---------------- fc2: 512->256, BN (no lrelu) -> d_out --------------------
__global__ void k_fc2(const float* __restrict__ fw, const float* __restrict__ fb,
                      const float* __restrict__ gam, const float* __restrict__ bet,
                      float* __restrict__ out) {
    int b = blockIdx.y;
    int w = threadIdx.x >> 5, lane = threadIdx.x & 31;
    int o = blockIdx.x * 8 + w;
    const float* f = g_fc1 + b * 512;
    const float* wr = fw + (size_t)o * 512;
    float acc = 0.f;
    for (int c = lane; c < 512; c += 32) acc = fmaf(f[c], wr[c], acc);
    #pragma unroll
    for (int s = 16; s > 0; s >>= 1) acc += __shfl_xor_sync(0xffffffffu, acc, s);
    if (lane == 0) {
        float v = acc + fb[o];
        out[b * 256 + o] = fmaf(v, gam[o] * BN_RSQ, bet[o]);
    }
}

// ---------------- driver ---------------------------------------------------
#define DT_SMEM ((8 * 64 + 8 * 256 + 64 * 256 + 64 * KNN * 2) * 4)

static void run_edge(const float* feat, int C, int bstr, const float* W,
                     const float* gam, const float* bet,
                     float* out, int Cout) {
    k_xx<<<(BATCH * NPTS + 255) / 256, 256>>>(feat, C, bstr);
    k_dist_topk<<<dim3(NPTS / 64, BATCH), 256, DT_SMEM>>>(feat, C, bstr);
    k_yz<<<dim3(NPTS / 64, Cout / 64, BATCH), 256>>>(feat, W, C, Cout, bstr);
    k_gather<<<dim3(NPTS / 32, BATCH), Cout>>>(out, gam, bet, Cout, CAT_BSTR);
}

extern "C" void kernel_launch(void* const* d_in, const int* in_sizes, int n_in,
                              void* d_out, int out_size) {
    const float* pts = (const float*)d_in[0];
    const float* w1 = (const float*)d_in[1];
    const float* g1 = (const float*)d_in[2];
    const float* b1 = (const float*)d_in[3];
    const float* w2 = (const float*)d_in[4];
    const float* g2 = (const float*)d_in[5];
    const float* b2 = (const float*)d_in[6];
    const float* w3 = (const float*)d_in[7];
    const float* g3 = (const float*)d_in[8];
    const float* b3 = (const float*)d_in[9];
    const float* w4 = (const float*)d_in[10];
    const float* g4 = (const float*)d_in[11];
    const float* b4 = (const float*)d_in[12];
    const float* w5 = (const float*)d_in[13];
    const float* g5 = (const float*)d_in[14];
    const float* b5 = (const float*)d_in[15];
    const float* fw1 = (const float*)d_in[16];
    const float* fb1 = (const float*)d_in[17];
    const float* g6 = (const float*)d_in[18];
    const float* b6 = (const float*)d_in[19];
    const float* fw2 = (const float*)d_in[20];
    const float* fb2 = (const float*)d_in[21];
    const float* g7 = (const float*)d_in[22];
    const float* b7 = (const float*)d_in[23];

    cudaFuncSetAttribute(k_dist_topk,
                         cudaFuncAttributeMaxDynamicSharedMemorySize, DT_SMEM);

    float *x0, *xcat;
    cudaGetSymbolAddress((void**)&x0, g_x0);
    cudaGetSymbolAddress((void**)&xcat, g_xcat);
    float* x1 = xcat;                  // ch 0..63
    float* x2 = xcat + 64 * NPTS;      // ch 64..127
    float* x3 = xcat + 128 * NPTS;     // ch 128..255
    float* x4 = xcat + 256 * NPTS;     // ch 256..511

    k_transpose<<<(BATCH * NPTS + 255) / 256, 256>>>(pts);
    run_edge(x0, 3,   3 * NPTS,  w1, g1, b1, x1, 64);
    run_edge(x1, 64,  CAT_BSTR,  w2, g2, b2, x2, 64);
    run_edge(x2, 64,  CAT_BSTR,  w3, g3, b3, x3, 128);
    run_edge(x3, 128, CAT_BSTR,  w4, g4, b4, x4, 256);
    k_conv5<<<dim3(NPTS / 128, 1024 / 128, BATCH), 256>>>(w5, g5, b5);
    k_pool<<<dim3(1024 / 256, BATCH), 256>>>();
    k_fc1<<<dim3(512 / 8, BATCH), 256>>>(fw1, fb1, g6, b6);
    k_fc2<<<dim3(256 / 8, BATCH), 256>>>(fw2, fb2, g7, b7, (float*)d_out);
}